// round 2
// baseline (speedup 1.0000x reference)
#include <cuda_runtime.h>
#include <cstdint>
#include <math_constants.h>

// Problem constants (fixed by the reference)
constexpr int NB = 16;     // batch
constexpr int LQ = 2048;   // query length
constexpr int SK = 2048;   // key length
constexpr int DD = 128;    // head dim

constexpr int TQ = 16;     // query rows per block (logits tile held in smem)
constexpr int TS = 128;    // s-tile width
constexpr int PAD = TS + 4;
constexpr int THREADS = 256;

// dynamic smem: logits[TQ][SK] | Qs[TQ][DD] | Ks[DD][PAD] (reused as V tile [TS][DD])
constexpr int SMEM_FLOATS = TQ * SK + TQ * DD + DD * PAD;

// Mask dtype: 0 = uint8 bool, 1 = int32, 2 = float32
__device__ int g_mask_kind;

__global__ void detect_mask_kind(const unsigned char* __restrict__ m)
{
    __shared__ int off1, off23;
    if (threadIdx.x == 0) { off1 = 0; off23 = 0; }
    __syncthreads();
    int b1 = 0, b23 = 0;
    for (int i = threadIdx.x; i < 16384; i += blockDim.x) {
        unsigned char v = m[i];
        int off = i & 3;
        if (v) {
            if (off == 1) b1 = 1;
            if (off == 2 || off == 3) b23 = 1;
        }
    }
    if (b1)  atomicOr(&off1, 1);
    if (b23) atomicOr(&off23, 1);
    __syncthreads();
    if (threadIdx.x == 0) {
        int kind;
        if (off1)       kind = 0;  // bytes populated at all offsets -> uint8 bool
        else if (off23) kind = 2;  // 0x3f80_0000 pattern -> float32
        else            kind = 1;  // nonzero only at offset 0 mod 4 -> int32
        g_mask_kind = kind;
    }
}

__device__ __forceinline__ bool mask_at(const void* M, int kind, size_t idx)
{
    if (kind == 0) return ((const unsigned char*)M)[idx] != 0;
    if (kind == 1) return ((const int*)M)[idx] != 0;
    return ((const float*)M)[idx] != 0.0f;
}

__global__ __launch_bounds__(THREADS, 1)
void attn_fused_kernel(const float* __restrict__ Q,
                       const float* __restrict__ K,
                       const float* __restrict__ V,
                       const void* __restrict__ M,
                       float* __restrict__ outX,
                       float* __restrict__ outW)
{
    extern __shared__ float sm[];
    float* Lg = sm;                    // TQ * SK   logits -> weights
    float* Qs = Lg + TQ * SK;          // TQ * DD
    float* Ks = Qs + TQ * DD;          // DD * PAD (transposed K tile) / V tile

    const int n   = blockIdx.y;
    const int q0  = blockIdx.x * TQ;
    const int tid = threadIdx.x;
    const int lane = tid & 31;
    const int wid  = tid >> 5;
    const int mkind = g_mask_kind;

    // ---- load Q tile (coalesced float4) ----
    const float* Qg = Q + ((size_t)n * LQ + q0) * DD;
    for (int i = tid; i < TQ * DD / 4; i += THREADS)
        ((float4*)Qs)[i] = ((const float4*)Qg)[i];

    const int sx = tid & 63;   // s-pair index (covers s = 2*sx, 2*sx+1)
    const int qy = tid >> 6;   // 0..3 -> q group (constant within a warp -> Qs broadcast)
    const float scale = 0.08838834764831845f;  // 1/sqrt(128)

    // ================= Phase 1: logits = mask ? -1e11 : clamp(QK^T * scale) =================
    for (int st = 0; st < SK; st += TS) {
        __syncthreads();  // previous Ks readers done
        const float* Kg = K + ((size_t)n * SK + st) * DD;
        // stage K tile transposed: Ks[k][s]
        for (int i = tid; i < TS * DD / 4; i += THREADS) {
            float4 v = ((const float4*)Kg)[i];
            int s = i >> 5;            // i / (DD/4)
            int k = (i & 31) << 2;
            Ks[(k + 0) * PAD + s] = v.x;
            Ks[(k + 1) * PAD + s] = v.y;
            Ks[(k + 2) * PAD + s] = v.z;
            Ks[(k + 3) * PAD + s] = v.w;
        }
        __syncthreads();

        float acc[4][2] = {};
        #pragma unroll 8
        for (int k = 0; k < DD; k += 2) {
            float2 kv0 = *(const float2*)&Ks[(k + 0) * PAD + 2 * sx];
            float2 kv1 = *(const float2*)&Ks[(k + 1) * PAD + 2 * sx];
            #pragma unroll
            for (int qi = 0; qi < 4; qi++) {
                float2 qv = *(const float2*)&Qs[(qy * 4 + qi) * DD + k];
                acc[qi][0] += qv.x * kv0.x + qv.y * kv1.x;
                acc[qi][1] += qv.x * kv0.y + qv.y * kv1.y;
            }
        }

        #pragma unroll
        for (int qi = 0; qi < 4; qi++) {
            int q = qy * 4 + qi;
            size_t mbase = ((size_t)(n * LQ + q0 + q)) * SK + st + 2 * sx;
            #pragma unroll
            for (int j = 0; j < 2; j++) {
                float l = fminf(fmaxf(acc[qi][j] * scale, -1e11f), 1e11f);
                if (mask_at(M, mkind, mbase + j)) l = -1e11f;  // clamp(-inf) = -1e11 exactly
                Lg[q * SK + st + 2 * sx + j] = l;
            }
        }
    }
    __syncthreads();

    // ================= Phase 2: row softmax in smem =================
    for (int r = wid; r < TQ; r += THREADS / 32) {
        float m = -CUDART_INF_F;
        for (int s = lane; s < SK; s += 32) m = fmaxf(m, Lg[r * SK + s]);
        #pragma unroll
        for (int o = 16; o; o >>= 1) m = fmaxf(m, __shfl_xor_sync(0xffffffffu, m, o));

        float sum = 0.f;
        for (int s = lane; s < SK; s += 32) {
            float e = expf(Lg[r * SK + s] - m);   // expf(-1e11 - m) -> exactly 0
            Lg[r * SK + s] = e;
            sum += e;
        }
        #pragma unroll
        for (int o = 16; o; o >>= 1) sum += __shfl_xor_sync(0xffffffffu, sum, o);

        float inv = 1.f / sum;
        for (int s = lane; s < SK; s += 32) Lg[r * SK + s] *= inv;
    }
    __syncthreads();

    // ---- write attn_weights (coalesced float4; smem layout == gmem layout) ----
    float* outWb = outW + ((size_t)(n * LQ + q0)) * SK;
    for (int i = tid; i < TQ * SK / 4; i += THREADS)
        ((float4*)outWb)[i] = ((const float4*)Lg)[i];

    // ================= Phase 3: x = weights @ V =================
    float xacc[4][2] = {};
    const int dx = tid & 63;  // d-pair index (d = 2*dx, 2*dx+1)
    for (int st = 0; st < SK; st += TS) {
        __syncthreads();  // previous V-tile readers done
        const float* Vg = V + ((size_t)n * SK + st) * DD;
        for (int i = tid; i < TS * DD / 4; i += THREADS)
            ((float4*)Ks)[i] = ((const float4*)Vg)[i];   // Vs[s][d], row stride DD
        __syncthreads();

        #pragma unroll 4
        for (int s = 0; s < TS; s++) {
            float2 vv = *(const float2*)&Ks[s * DD + 2 * dx];
            #pragma unroll
            for (int qi = 0; qi < 4; qi++) {
                float w = Lg[(qy * 4 + qi) * SK + st + s];  // warp-broadcast
                xacc[qi][0] += w * vv.x;
                xacc[qi][1] += w * vv.y;
            }
        }
    }

    #pragma unroll
    for (int qi = 0; qi < 4; qi++) {
        int q = qy * 4 + qi;
        float2 o;
        o.x = xacc[qi][0];
        o.y = xacc[qi][1];
        *(float2*)&outX[((size_t)(n * LQ + q0 + q)) * DD + 2 * dx] = o;
    }
}

extern "C" void kernel_launch(void* const* d_in, const int* in_sizes, int n_in,
                              void* d_out, int out_size)
{
    (void)in_sizes; (void)n_in; (void)out_size;
    const float* Q = (const float*)d_in[0];
    const float* K = (const float*)d_in[1];
    const float* V = (const float*)d_in[2];
    const void*  M = d_in[3];

    float* outX = (float*)d_out;                       // (N, L, D) first
    float* outW = outX + (size_t)NB * LQ * DD;         // (N, L, S) second

    cudaFuncSetAttribute(attn_fused_kernel,
                         cudaFuncAttributeMaxDynamicSharedMemorySize,
                         SMEM_FLOATS * (int)sizeof(float));

    detect_mask_kind<<<1, 256>>>((const unsigned char*)M);

    dim3 grid(LQ / TQ, NB);
    attn_fused_kernel<<<grid, THREADS, SMEM_FLOATS * sizeof(float)>>>(
        Q, K, V, M, outX, outW);
}